// round 10
// baseline (speedup 1.0000x reference)
#include <cuda_runtime.h>

#define B  16
#define T2 2048
#define T1 512
#define F  128
#define NROWS (B * T2)

// scratch (allocation-free rule: __device__ globals)
__device__ float g_prop[NROWS];
__device__ float g_act [NROWS];
__device__ float g_imv [NROWS];
__device__ float g_zinv[NROWS];
__device__ float g_m   [NROWS];
__device__ int   g_vlen[B];

__device__ __forceinline__ float wred(float v) {
#pragma unroll
    for (int o = 16; o; o >>= 1) v += __shfl_xor_sync(0xffffffffu, v, o);
    return v;
}
__device__ __forceinline__ int wredi(int v) {
#pragma unroll
    for (int o = 16; o; o >>= 1) v += __shfl_xor_sync(0xffffffffu, v, o);
    return v;
}

// tf32 round-to-nearest (matches cuBLAS f32->tf32 input conversion)
__device__ __forceinline__ float tf32r(float x) {
    float y;
    asm("cvt.rna.tf32.f32 %0, %1;" : "=f"(y) : "f"(x));
    return y;
}

// Neumaier compensated add: (sum, comp) += x
__device__ __forceinline__ void neum_add(float& sum, float& comp, float x) {
    float t = sum + x;
    float corr = (fabsf(sum) >= fabsf(x)) ? ((sum - t) + x) : ((x - t) + sum);
    comp += corr;
    sum = t;
}

// ---------------------------------------------------------------------------
// Kernel 1: one warp per (b,t) row.
//  - imv_proposal = sum_s alpha[b,t,s]*s via 4 INDEPENDENT compensated
//    chains (ILP) merged at the end  -> near-exact, f32 pipe only.
//  - activity = sigmoid(10*(0.9 - cos(mel[t-1], mel[t]))) * am
// ---------------------------------------------------------------------------
__global__ void k_prop_act(const float* __restrict__ mels,
                           const float* __restrict__ alpha,
                           const int*   __restrict__ mmask) {
    int warp = (blockIdx.x * blockDim.x + threadIdx.x) >> 5;
    int lane = threadIdx.x & 31;
    if (warp >= NROWS) return;
    int t = warp % T2;

    const float4* a4 = (const float4*)(alpha + (size_t)warp * T1);
    float sum0 = 0.f, c0 = 0.f;
    float sum1 = 0.f, c1 = 0.f;
    float sum2 = 0.f, c2 = 0.f;
    float sum3 = 0.f, c3 = 0.f;
#pragma unroll
    for (int i = 0; i < 4; i++) {
        int idx = lane + i * 32;          // 0..127 float4 per row
        float4 v = a4[idx];
        float s = (float)(idx * 4);
        {   // independent chain 0
            float p = v.x * s;
            float e = fmaf(v.x, s, -p);
            neum_add(sum0, c0, p); c0 += e;
        }
        {   // chain 1
            float s1 = s + 1.f;
            float p = v.y * s1;
            float e = fmaf(v.y, s1, -p);
            neum_add(sum1, c1, p); c1 += e;
        }
        {   // chain 2
            float s2 = s + 2.f;
            float p = v.z * s2;
            float e = fmaf(v.z, s2, -p);
            neum_add(sum2, c2, p); c2 += e;
        }
        {   // chain 3
            float s3 = s + 3.f;
            float p = v.w * s3;
            float e = fmaf(v.w, s3, -p);
            neum_add(sum3, c3, p); c3 += e;
        }
    }
    // merge the 4 chains with compensation
    float S = sum0, C = c0;
    neum_add(S, C, sum1); C += c1;
    neum_add(S, C, sum2); C += c2;
    neum_add(S, C, sum3); C += c3;

    // compensated warp reduction of (S, C) pairs
#pragma unroll
    for (int o = 16; o; o >>= 1) {
        float oh = __shfl_xor_sync(0xffffffffu, S, o);
        float ol = __shfl_xor_sync(0xffffffffu, C, o);
        float tt = S + oh;
        float corr = (fabsf(S) >= fabsf(oh)) ? ((S - tt) + oh) : ((oh - tt) + S);
        S = tt;
        C = C + ol + corr;
    }
    float prop = S + C;

    float am = (float)mmask[warp];
    float act;
    if (t == 0) {
        act = am;
    } else {
        const float4* m1 = (const float4*)(mels + (size_t)warp * F);
        const float4* m0 = (const float4*)(mels + (size_t)(warp - 1) * F);
        float4 x = m1[lane], y = m0[lane];   // F=128 -> exactly 1 float4/lane
        float dot = x.x * y.x + x.y * y.y + x.z * y.z + x.w * y.w;
        float n1  = x.x * x.x + x.y * x.y + x.z * x.z + x.w * x.w;
        float n0  = y.x * y.x + y.y * y.y + y.z * y.z + y.w * y.w;
        dot = wred(dot); n1 = wred(n1); n0 = wred(n0);
        float c = dot / (fmaxf(sqrtf(n0), 1e-12f) * fmaxf(sqrtf(n1), 1e-12f));
        float z = 10.f * (0.9f - c);
        act = am / (1.f + __expf(-z));
    }
    if (lane == 0) { g_prop[warp] = prop; g_act[warp] = act; }
}

// ---------------------------------------------------------------------------
// Kernel 2: scan only (per-batch). eff_delta in f32 (ref op order), prefix
// scan carried in double (exact), rescale, write final imv.
// ---------------------------------------------------------------------------
__global__ void k_scan(const int* __restrict__ mmask,
                       const int* __restrict__ tmask,
                       float* __restrict__ imv_out) {
    int b    = blockIdx.x;
    int tid  = threadIdx.x;       // 256
    int lane = tid & 31, wid = tid >> 5;
    const float* prop = g_prop + b * T2;
    const float* act  = g_act  + b * T2;
    const int*   mm   = mmask  + b * T2;

    __shared__ float  s_imv[T2];
    __shared__ double wsum[8];
    __shared__ int    s_msum, s_tsum;
    __shared__ float  s_scale;
    if (tid == 0) { s_msum = 0; s_tsum = 0; }
    __syncthreads();

    double vals[8];
    double run = 0.0;
    int    msum = 0;
#pragma unroll
    for (int j = 0; j < 8; j++) {
        int t = tid * 8 + j;
        float e = 0.f;
        if (t > 0) {
            e = (prop[t] - prop[t - 1]) * act[t];   // f32, as in reference
            e = fminf(fmaxf(e, 0.f), 1.f);
        }
        run += (double)e;
        vals[j] = run;
        msum += mm[t];
    }
    double tot = run;
#pragma unroll
    for (int o = 1; o < 32; o <<= 1) {
        double n = __shfl_up_sync(0xffffffffu, tot, o);
        if (lane >= o) tot += n;
    }
    if (lane == 31) wsum[wid] = tot;

    msum = wredi(msum);
    if (lane == 0) atomicAdd(&s_msum, msum);
    int tsum = tmask[b * T1 + tid] + tmask[b * T1 + 256 + tid];
    tsum = wredi(tsum);
    if (lane == 0) atomicAdd(&s_tsum, tsum);
    __syncthreads();

    if (wid == 0 && lane < 8) {
        double w = wsum[lane];
#pragma unroll
        for (int o = 1; o < 8; o <<= 1) {
            double n = __shfl_up_sync(0x000000ffu, w, o);
            if (lane >= o) w += n;
        }
        wsum[lane] = w;
    }
    __syncthreads();

    double base = (wid > 0 ? wsum[wid - 1] : 0.0) + (tot - run);
#pragma unroll
    for (int j = 0; j < 8; j++) s_imv[tid * 8 + j] = (float)(base + vals[j]);
    __syncthreads();

    if (tid == 0) {
        int vlen = s_msum;
        g_vlen[b] = vlen;
        int li = vlen - 1; if (li < 0) li = 0;
        float lastv = fmaxf(s_imv[li] * (float)mm[li], 1e-6f);
        float tl = (float)s_tsum;
        s_scale = fmaxf(tl - 1.f, 0.f) / lastv;   // f32 divide, as in ref
    }
    __syncthreads();

    float sc = s_scale;
#pragma unroll
    for (int j = 0; j < 8; j++) {
        int t = tid * 8 + j;
        float v = s_imv[t] * sc * (float)mm[t];   // f32 mul chain, as in ref
        g_imv[b * T2 + t]   = v;
        imv_out[b * T2 + t] = v;
    }
}

// ---------------------------------------------------------------------------
// Kernel 3: per-frame softmax normalizer over +/-4 window (full-chip grid).
// ---------------------------------------------------------------------------
__global__ void k_z(const int* __restrict__ mmask,
                    const int* __restrict__ tmask) {
    int r = blockIdx.x * blockDim.x + threadIdx.x;
    if (r >= NROWS) return;
    int b = r / T2;
    float x  = g_imv[r];
    float am = (float)mmask[r];
    const int* tm = tmask + b * T1;
    int ci = (int)floorf(x + 0.5f);
    float l[9];
    float m = -1e30f;
#pragma unroll
    for (int k = 0; k < 9; k++) {
        int s = ci + k - 4;
        float lv = -1e30f;
        if (s >= 0 && s < T1 && tm[s]) {
            float d = x - (float)s;
            lv = -10.f * d * d;
        }
        l[k] = lv;
        m = fmaxf(m, lv);
    }
    float Z = 0.f;
#pragma unroll
    for (int k = 0; k < 9; k++)
        if (l[k] > -1e29f) Z += __expf(l[k] - m);
    g_m[r]    = m;
    g_zinv[r] = (Z > 0.f) ? am / Z : 0.f;
}

// ---------------------------------------------------------------------------
// Kernel 4: gather. Block = (8 phonemes, 1 batch), 256 threads = 2 halves
// of 128 feature lanes. Each half processes half the t-support (halved
// serial loop, doubled warps/SM); partials merged in shared.
// Phase A: durations (f32). Phase B: TF32-emulated attention pooling.
// ---------------------------------------------------------------------------
__global__ void __launch_bounds__(256) k_gather(
        const float* __restrict__ mels,
        const int*   __restrict__ tmask,
        float* __restrict__ aligned,
        float* __restrict__ durs) {
    int b    = blockIdx.y;
    int s0   = blockIdx.x * 8;
    int x    = threadIdx.x;        // 0..255
    int tid  = x & 127;            // feature lane
    int half = x >> 7;             // 0 or 1
    const float* imv = g_imv + b * T2;
    int vlen = g_vlen[b];

    // binary search for t-range where any of s0..s0+7 can get nonzero gamma
    float lob = (float)s0 - 4.6f;
    float hib = (float)(s0 + 7) + 4.6f;
    int lo = 0, hi = vlen;
    while (lo < hi) { int mid = (lo + hi) >> 1; if (imv[mid] < lob) lo = mid + 1; else hi = mid; }
    int t_lo = lo;
    lo = t_lo; hi = vlen;
    while (lo < hi) { int mid = (lo + hi) >> 1; if (imv[mid] <= hib) lo = mid + 1; else hi = mid; }
    int t_hi = lo;
    int nt_all = t_hi - t_lo;

    __shared__ float s_g[2][8][132];
    __shared__ float s_acc[8][128];
    __shared__ float s_tm[8];
    __shared__ float s_w[8][8];
    __shared__ float s_dur[8];
    if (x < 8) s_tm[x] = (float)tmask[b * T1 + s0 + x];
    __syncthreads();

    // ---- Phase A: durations, all 256 threads stride the range ----
    float durp[8];
#pragma unroll
    for (int k = 0; k < 8; k++) durp[k] = 0.f;
    for (int t = t_lo + x; t < t_hi; t += 256) {
        float xv = imv[t];
        float zi = g_zinv[b * T2 + t];
        float mm = g_m[b * T2 + t];
#pragma unroll
        for (int k = 0; k < 8; k++) {
            float d  = xv - (float)(s0 + k);
            float arg = fminf(-10.f * d * d - mm, 80.f);
            durp[k] += __expf(arg) * zi * s_tm[k];
        }
    }
#pragma unroll
    for (int k = 0; k < 8; k++) durp[k] = wred(durp[k]);
    int lane = x & 31, wid = x >> 5;   // 8 warps
    if (lane == 0) {
#pragma unroll
        for (int k = 0; k < 8; k++) s_w[wid][k] = durp[k];
    }
    __syncthreads();
    if (x < 8) {
        float d = 0.f;
#pragma unroll
        for (int w = 0; w < 8; w++) d += s_w[w][x];
        s_dur[x] = d;
        durs[b * T1 + s0 + x] = d * s_tm[x];
    }
    __syncthreads();

    float invd[8];
#pragma unroll
    for (int k = 0; k < 8; k++) invd[k] = s_dur[k] + 1e-8f;

    // ---- Phase B: split t-range between the two halves ----
    int half_n = (nt_all + 1) >> 1;            // half0 >= half1
    int lo_h = t_lo + half * half_n;
    int hi_h = t_lo + (half ? nt_all : half_n);
    int n_ch = (half_n + 127) >> 7;            // uniform chunk count

    float acc[8];
#pragma unroll
    for (int k = 0; k < 8; k++) acc[k] = 0.f;

    for (int c = 0; c < n_ch; c++) {
        int t0 = lo_h + c * 128;
        int t  = t0 + tid;
        if (t < hi_h) {
            float xv = imv[t];
            float zi = g_zinv[b * T2 + t];
            float mm = g_m[b * T2 + t];
#pragma unroll
            for (int k = 0; k < 8; k++) {
                float d  = xv - (float)(s0 + k);
                float arg = fminf(-10.f * d * d - mm, 80.f);
                float g   = __expf(arg) * zi * s_tm[k];
                s_g[half][k][tid] = tf32r(g / invd[k]);  // normalized -> tf32
            }
        } else {
#pragma unroll
            for (int k = 0; k < 8; k++) s_g[half][k][tid] = 0.f;
        }
        __syncthreads();

        int nt = hi_h - t0;
        if (nt > 128) nt = 128;
        if (nt > 0) {
            const float* mp = mels + ((size_t)(b * T2 + t0)) * F + tid;
            for (int tt = 0; tt < nt; tt++) {
                float mv = tf32r(mp[(size_t)tt * F]);    // mel -> tf32
#pragma unroll
                for (int k = 0; k < 8; k++)
                    acc[k] = fmaf(s_g[half][k][tt], mv, acc[k]);
            }
        }
        __syncthreads();
    }

    // merge halves
    if (half == 1) {
#pragma unroll
        for (int k = 0; k < 8; k++) s_acc[k][tid] = acc[k];
    }
    __syncthreads();
    if (half == 0) {
#pragma unroll
        for (int k = 0; k < 8; k++) {
            aligned[((size_t)(b * T1 + s0 + k)) * F + tid] =
                (acc[k] + s_acc[k][tid]) * s_tm[k];
        }
    }
}

// ---------------------------------------------------------------------------
extern "C" void kernel_launch(void* const* d_in, const int* in_sizes, int n_in,
                              void* d_out, int out_size) {
    const float* mels  = (const float*)d_in[0];
    const float* alpha = (const float*)d_in[1];
    const int*   mmask = (const int*)d_in[2];
    const int*   tmask = (const int*)d_in[3];

    float* out_al  = (float*)d_out;                       // [B,T1,F]
    float* out_dur = out_al + (size_t)B * T1 * F;         // [B,T1]
    float* out_imv = out_dur + (size_t)B * T1;            // [B,T2]

    (void)in_sizes; (void)n_in; (void)out_size;

    // 1) proposal + activity : 1 warp per (b,t)
    {
        int warps = NROWS;
        int threads = 256;
        int blocks = (warps * 32 + threads - 1) / threads;
        k_prop_act<<<blocks, threads>>>(mels, alpha, mmask);
    }
    // 2) scan + rescale : 1 block per batch
    k_scan<<<B, 256>>>(mmask, tmask, out_imv);
    // 3) softmax normalizers : full-chip
    k_z<<<NROWS / 256, 256>>>(mmask, tmask);
    // 4) gather: aligned_mels + durations
    {
        dim3 grid(T1 / 8, B);
        k_gather<<<grid, 256>>>(mels, tmask, out_al, out_dur);
    }
}

// round 14
// speedup vs baseline: 1.1477x; 1.1477x over previous
#include <cuda_runtime.h>

#define B  16
#define T2 2048
#define T1 512
#define F  128
#define NROWS (B * T2)

// scratch (allocation-free rule: __device__ globals)
__device__ float g_prop[NROWS];
__device__ float g_act [NROWS];
__device__ float g_imv [NROWS];
__device__ float g_zinv[NROWS];
__device__ float g_m   [NROWS];
__device__ int   g_vlen[B];

__device__ __forceinline__ float wred(float v) {
#pragma unroll
    for (int o = 16; o; o >>= 1) v += __shfl_xor_sync(0xffffffffu, v, o);
    return v;
}
__device__ __forceinline__ int wredi(int v) {
#pragma unroll
    for (int o = 16; o; o >>= 1) v += __shfl_xor_sync(0xffffffffu, v, o);
    return v;
}

// tf32 round-to-nearest (matches cuBLAS f32->tf32 input conversion)
__device__ __forceinline__ float tf32r(float x) {
    float y;
    asm("cvt.rna.tf32.f32 %0, %1;" : "=f"(y) : "f"(x));
    return y;
}

// Neumaier compensated add: (sum, comp) += x
__device__ __forceinline__ void neum_add(float& sum, float& comp, float x) {
    float t = sum + x;
    float corr = (fabsf(sum) >= fabsf(x)) ? ((sum - t) + x) : ((x - t) + sum);
    comp += corr;
    sum = t;
}

// ---------------------------------------------------------------------------
// Kernel 1: one warp per (b,t) row.  (unchanged from R9 — validated)
// ---------------------------------------------------------------------------
__global__ void k_prop_act(const float* __restrict__ mels,
                           const float* __restrict__ alpha,
                           const int*   __restrict__ mmask) {
    int warp = (blockIdx.x * blockDim.x + threadIdx.x) >> 5;
    int lane = threadIdx.x & 31;
    if (warp >= NROWS) return;
    int t = warp % T2;

    const float4* a4 = (const float4*)(alpha + (size_t)warp * T1);
    float sum0 = 0.f, c0 = 0.f;
    float sum1 = 0.f, c1 = 0.f;
    float sum2 = 0.f, c2 = 0.f;
    float sum3 = 0.f, c3 = 0.f;
#pragma unroll
    for (int i = 0; i < 4; i++) {
        int idx = lane + i * 32;          // 0..127 float4 per row
        float4 v = a4[idx];
        float s = (float)(idx * 4);
        {
            float p = v.x * s;
            float e = fmaf(v.x, s, -p);
            neum_add(sum0, c0, p); c0 += e;
        }
        {
            float s1 = s + 1.f;
            float p = v.y * s1;
            float e = fmaf(v.y, s1, -p);
            neum_add(sum1, c1, p); c1 += e;
        }
        {
            float s2 = s + 2.f;
            float p = v.z * s2;
            float e = fmaf(v.z, s2, -p);
            neum_add(sum2, c2, p); c2 += e;
        }
        {
            float s3 = s + 3.f;
            float p = v.w * s3;
            float e = fmaf(v.w, s3, -p);
            neum_add(sum3, c3, p); c3 += e;
        }
    }
    float S = sum0, C = c0;
    neum_add(S, C, sum1); C += c1;
    neum_add(S, C, sum2); C += c2;
    neum_add(S, C, sum3); C += c3;

#pragma unroll
    for (int o = 16; o; o >>= 1) {
        float oh = __shfl_xor_sync(0xffffffffu, S, o);
        float ol = __shfl_xor_sync(0xffffffffu, C, o);
        float tt = S + oh;
        float corr = (fabsf(S) >= fabsf(oh)) ? ((S - tt) + oh) : ((oh - tt) + S);
        S = tt;
        C = C + ol + corr;
    }
    float prop = S + C;

    float am = (float)mmask[warp];
    float act;
    if (t == 0) {
        act = am;
    } else {
        const float4* m1 = (const float4*)(mels + (size_t)warp * F);
        const float4* m0 = (const float4*)(mels + (size_t)(warp - 1) * F);
        float4 x = m1[lane], y = m0[lane];
        float dot = x.x * y.x + x.y * y.y + x.z * y.z + x.w * y.w;
        float n1  = x.x * x.x + x.y * x.y + x.z * x.z + x.w * x.w;
        float n0  = y.x * y.x + y.y * y.y + y.z * y.z + y.w * y.w;
        dot = wred(dot); n1 = wred(n1); n0 = wred(n0);
        float c = dot / (fmaxf(sqrtf(n0), 1e-12f) * fmaxf(sqrtf(n1), 1e-12f));
        float z = 10.f * (0.9f - c);
        act = am / (1.f + __expf(-z));
    }
    if (lane == 0) { g_prop[warp] = prop; g_act[warp] = act; }
}

// ---------------------------------------------------------------------------
// Kernel 2: per-batch scan + rescale (unchanged from R9 — validated)
// ---------------------------------------------------------------------------
__global__ void k_scan(const int* __restrict__ mmask,
                       const int* __restrict__ tmask,
                       float* __restrict__ imv_out) {
    int b    = blockIdx.x;
    int tid  = threadIdx.x;       // 256
    int lane = tid & 31, wid = tid >> 5;
    const float* prop = g_prop + b * T2;
    const float* act  = g_act  + b * T2;
    const int*   mm   = mmask  + b * T2;

    __shared__ float  s_imv[T2];
    __shared__ double wsum[8];
    __shared__ int    s_msum, s_tsum;
    __shared__ float  s_scale;
    if (tid == 0) { s_msum = 0; s_tsum = 0; }
    __syncthreads();

    double vals[8];
    double run = 0.0;
    int    msum = 0;
#pragma unroll
    for (int j = 0; j < 8; j++) {
        int t = tid * 8 + j;
        float e = 0.f;
        if (t > 0) {
            e = (prop[t] - prop[t - 1]) * act[t];   // f32, as in reference
            e = fminf(fmaxf(e, 0.f), 1.f);
        }
        run += (double)e;
        vals[j] = run;
        msum += mm[t];
    }
    double tot = run;
#pragma unroll
    for (int o = 1; o < 32; o <<= 1) {
        double n = __shfl_up_sync(0xffffffffu, tot, o);
        if (lane >= o) tot += n;
    }
    if (lane == 31) wsum[wid] = tot;

    msum = wredi(msum);
    if (lane == 0) atomicAdd(&s_msum, msum);
    int tsum = tmask[b * T1 + tid] + tmask[b * T1 + 256 + tid];
    tsum = wredi(tsum);
    if (lane == 0) atomicAdd(&s_tsum, tsum);
    __syncthreads();

    if (wid == 0 && lane < 8) {
        double w = wsum[lane];
#pragma unroll
        for (int o = 1; o < 8; o <<= 1) {
            double n = __shfl_up_sync(0x000000ffu, w, o);
            if (lane >= o) w += n;
        }
        wsum[lane] = w;
    }
    __syncthreads();

    double base = (wid > 0 ? wsum[wid - 1] : 0.0) + (tot - run);
#pragma unroll
    for (int j = 0; j < 8; j++) s_imv[tid * 8 + j] = (float)(base + vals[j]);
    __syncthreads();

    if (tid == 0) {
        int vlen = s_msum;
        g_vlen[b] = vlen;
        int li = vlen - 1; if (li < 0) li = 0;
        float lastv = fmaxf(s_imv[li] * (float)mm[li], 1e-6f);
        float tl = (float)s_tsum;
        s_scale = fmaxf(tl - 1.f, 0.f) / lastv;   // f32 divide, as in ref
    }
    __syncthreads();

    float sc = s_scale;
#pragma unroll
    for (int j = 0; j < 8; j++) {
        int t = tid * 8 + j;
        float v = s_imv[t] * sc * (float)mm[t];   // f32 mul chain, as in ref
        g_imv[b * T2 + t]   = v;
        imv_out[b * T2 + t] = v;
    }
}

// ---------------------------------------------------------------------------
// Kernel 3: per-frame softmax normalizer (unchanged from R9 — validated)
// ---------------------------------------------------------------------------
__global__ void k_z(const int* __restrict__ mmask,
                    const int* __restrict__ tmask) {
    int r = blockIdx.x * blockDim.x + threadIdx.x;
    if (r >= NROWS) return;
    int b = r / T2;
    float x  = g_imv[r];
    float am = (float)mmask[r];
    const int* tm = tmask + b * T1;
    int ci = (int)floorf(x + 0.5f);
    float l[9];
    float m = -1e30f;
#pragma unroll
    for (int k = 0; k < 9; k++) {
        int s = ci + k - 4;
        float lv = -1e30f;
        if (s >= 0 && s < T1 && tm[s]) {
            float d = x - (float)s;
            lv = -10.f * d * d;
        }
        l[k] = lv;
        m = fmaxf(m, lv);
    }
    float Z = 0.f;
#pragma unroll
    for (int k = 0; k < 9; k++)
        if (l[k] > -1e29f) Z += __expf(l[k] - m);
    g_m[r]    = m;
    g_zinv[r] = (Z > 0.f) ? am / Z : 0.f;
}

// ---------------------------------------------------------------------------
// Kernel 4: gather. Block = (4 phonemes, 1 batch), 128 threads = F lanes.
// Tile shrunk 8->4: grid doubles to 2048 blocks (occupancy was grid-limited
// at 1024), serial t-support per block shrinks ~69->~53 frames, regs drop.
// Phase A: durations (f32). Phase B: TF32-emulated attention pooling.
// ---------------------------------------------------------------------------
#define SPB 4   // phonemes per block
__global__ void __launch_bounds__(128) k_gather(
        const float* __restrict__ mels,
        const int*   __restrict__ tmask,
        float* __restrict__ aligned,
        float* __restrict__ durs) {
    int b   = blockIdx.y;
    int s0  = blockIdx.x * SPB;
    int tid = threadIdx.x;
    const float* imv = g_imv + b * T2;
    int vlen = g_vlen[b];

    // binary search for t-range where any of s0..s0+SPB-1 can get nonzero gamma
    float lob = (float)s0 - 4.6f;
    float hib = (float)(s0 + SPB - 1) + 4.6f;
    int lo = 0, hi = vlen;
    while (lo < hi) { int mid = (lo + hi) >> 1; if (imv[mid] < lob) lo = mid + 1; else hi = mid; }
    int t_lo = lo;
    lo = t_lo; hi = vlen;
    while (lo < hi) { int mid = (lo + hi) >> 1; if (imv[mid] <= hib) lo = mid + 1; else hi = mid; }
    int t_hi = lo;

    __shared__ float s_g[SPB][132];
    __shared__ float s_tm[SPB];
    __shared__ float s_w[4][SPB];
    __shared__ float s_dur[SPB];
    if (tid < SPB) s_tm[tid] = (float)tmask[b * T1 + s0 + tid];
    __syncthreads();

    float durp[SPB];
#pragma unroll
    for (int k = 0; k < SPB; k++) durp[k] = 0.f;

    // ---- Phase A: durations (unnormalized gamma mass per phoneme) ----
    for (int t = t_lo + tid; t < t_hi; t += 128) {
        float x  = imv[t];
        float zi = g_zinv[b * T2 + t];
        float mm = g_m[b * T2 + t];
#pragma unroll
        for (int k = 0; k < SPB; k++) {
            float d  = x - (float)(s0 + k);
            float arg = fminf(-10.f * d * d - mm, 80.f);
            durp[k] += __expf(arg) * zi * s_tm[k];
        }
    }
#pragma unroll
    for (int k = 0; k < SPB; k++) durp[k] = wred(durp[k]);
    int lane = tid & 31, wid = tid >> 5;
    if (lane == 0) {
#pragma unroll
        for (int k = 0; k < SPB; k++) s_w[wid][k] = durp[k];
    }
    __syncthreads();
    if (tid < SPB) {
        float d = s_w[0][tid] + s_w[1][tid] + s_w[2][tid] + s_w[3][tid];
        s_dur[tid] = d;
        durs[b * T1 + s0 + tid] = d * s_tm[tid];
    }
    __syncthreads();

    float invd[SPB];
#pragma unroll
    for (int k = 0; k < SPB; k++) invd[k] = s_dur[k] + 1e-8f;

    // ---- Phase B: TF32-emulated attention pooling ----
    float acc[SPB];
#pragma unroll
    for (int k = 0; k < SPB; k++) acc[k] = 0.f;

    for (int t0 = t_lo; t0 < t_hi; t0 += 128) {
        int t = t0 + tid;
        if (t < t_hi) {
            float x  = imv[t];
            float zi = g_zinv[b * T2 + t];
            float mm = g_m[b * T2 + t];
#pragma unroll
            for (int k = 0; k < SPB; k++) {
                float d  = x - (float)(s0 + k);
                float arg = fminf(-10.f * d * d - mm, 80.f);
                float g   = __expf(arg) * zi * s_tm[k];
                s_g[k][tid] = tf32r(g / invd[k]);   // normalized weight -> tf32
            }
        } else {
#pragma unroll
            for (int k = 0; k < SPB; k++) s_g[k][tid] = 0.f;
        }
        __syncthreads();

        int nt = t_hi - t0; if (nt > 128) nt = 128;
        const float* mp = mels + ((size_t)(b * T2 + t0)) * F + tid;
#pragma unroll 4
        for (int tt = 0; tt < nt; tt++) {
            float mv = tf32r(mp[(size_t)tt * F]);   // mel operand -> tf32
#pragma unroll
            for (int k = 0; k < SPB; k++) acc[k] = fmaf(s_g[k][tt], mv, acc[k]);
        }
        __syncthreads();
    }

#pragma unroll
    for (int k = 0; k < SPB; k++) {
        aligned[((size_t)(b * T1 + s0 + k)) * F + tid] = acc[k] * s_tm[k];
    }
}

// ---------------------------------------------------------------------------
extern "C" void kernel_launch(void* const* d_in, const int* in_sizes, int n_in,
                              void* d_out, int out_size) {
    const float* mels  = (const float*)d_in[0];
    const float* alpha = (const float*)d_in[1];
    const int*   mmask = (const int*)d_in[2];
    const int*   tmask = (const int*)d_in[3];

    float* out_al  = (float*)d_out;                       // [B,T1,F]
    float* out_dur = out_al + (size_t)B * T1 * F;         // [B,T1]
    float* out_imv = out_dur + (size_t)B * T1;            // [B,T2]

    (void)in_sizes; (void)n_in; (void)out_size;

    // 1) proposal + activity : 1 warp per (b,t)
    {
        int warps = NROWS;
        int threads = 256;
        int blocks = (warps * 32 + threads - 1) / threads;
        k_prop_act<<<blocks, threads>>>(mels, alpha, mmask);
    }
    // 2) scan + rescale : 1 block per batch
    k_scan<<<B, 256>>>(mmask, tmask, out_imv);
    // 3) softmax normalizers : full-chip
    k_z<<<NROWS / 256, 256>>>(mmask, tmask);
    // 4) gather: aligned_mels + durations (4 phonemes/block, 2048 blocks)
    {
        dim3 grid(T1 / SPB, B);
        k_gather<<<grid, 128>>>(mels, tmask, out_al, out_dur);
    }
}

// round 16
// speedup vs baseline: 1.4517x; 1.2649x over previous
#include <cuda_runtime.h>

#define B  16
#define T2 2048
#define T1 512
#define F  128
#define NROWS (B * T2)
#define SPB 8   // phonemes per gather block

// scratch (allocation-free rule: __device__ globals)
__device__ float  g_prop[NROWS];
__device__ float  g_act [NROWS];
__device__ float  g_imv [NROWS];
__device__ float2 g_iw  [NROWS];   // (imv, w = am*exp(-m)/Z) packed
__device__ int    g_vlen[B];

__device__ __forceinline__ float wred(float v) {
#pragma unroll
    for (int o = 16; o; o >>= 1) v += __shfl_xor_sync(0xffffffffu, v, o);
    return v;
}
__device__ __forceinline__ int wredi(int v) {
#pragma unroll
    for (int o = 16; o; o >>= 1) v += __shfl_xor_sync(0xffffffffu, v, o);
    return v;
}

// tf32 round-to-nearest (matches cuBLAS f32->tf32 input conversion)
__device__ __forceinline__ float tf32r(float x) {
    float y;
    asm("cvt.rna.tf32.f32 %0, %1;" : "=f"(y) : "f"(x));
    return y;
}

// Neumaier compensated add: (sum, comp) += x
__device__ __forceinline__ void neum_add(float& sum, float& comp, float x) {
    float t = sum + x;
    float corr = (fabsf(sum) >= fabsf(x)) ? ((sum - t) + x) : ((x - t) + sum);
    comp += corr;
    sum = t;
}

// Warp-cooperative 32-ary search over monotone a[0..n).x
// upper=false: first idx with a[idx].x >= key ; upper=true: first with > key.
__device__ __forceinline__ int wsearch(const float2* __restrict__ a, int n,
                                       float key, bool upper, int lane) {
    int lo = 0, hi = n;
    while (hi - lo > 32) {
        int len = hi - lo;
        int chunk = (len + 31) >> 5;
        int pos = lo + lane * chunk;
        bool pred = false;
        if (pos < hi) {
            float v = a[pos].x;
            pred = upper ? (v <= key) : (v < key);
        }
        unsigned mask = __ballot_sync(0xffffffffu, pred);
        if (mask == 0) return lo;          // a[lo] already past key
        int L = 31 - __clz(mask);
        int nhi = lo + (L + 1) * chunk; if (nhi > hi) nhi = hi;
        lo = lo + L * chunk + 1;
        hi = nhi;
    }
    {
        int pos = lo + lane;
        bool pred = false;
        if (pos < hi) {
            float v = a[pos].x;
            pred = upper ? (v <= key) : (v < key);
        }
        unsigned mask = __ballot_sync(0xffffffffu, pred);
        return lo + __popc(mask);          // preds form a prefix (monotone a)
    }
}

// ---------------------------------------------------------------------------
// Kernel 1: one warp per (b,t) row.  (unchanged — validated)
// ---------------------------------------------------------------------------
__global__ void k_prop_act(const float* __restrict__ mels,
                           const float* __restrict__ alpha,
                           const int*   __restrict__ mmask) {
    int warp = (blockIdx.x * blockDim.x + threadIdx.x) >> 5;
    int lane = threadIdx.x & 31;
    if (warp >= NROWS) return;
    int t = warp % T2;

    const float4* a4 = (const float4*)(alpha + (size_t)warp * T1);
    float sum0 = 0.f, c0 = 0.f;
    float sum1 = 0.f, c1 = 0.f;
    float sum2 = 0.f, c2 = 0.f;
    float sum3 = 0.f, c3 = 0.f;
#pragma unroll
    for (int i = 0; i < 4; i++) {
        int idx = lane + i * 32;
        float4 v = a4[idx];
        float s = (float)(idx * 4);
        {
            float p = v.x * s;
            float e = fmaf(v.x, s, -p);
            neum_add(sum0, c0, p); c0 += e;
        }
        {
            float s1 = s + 1.f;
            float p = v.y * s1;
            float e = fmaf(v.y, s1, -p);
            neum_add(sum1, c1, p); c1 += e;
        }
        {
            float s2 = s + 2.f;
            float p = v.z * s2;
            float e = fmaf(v.z, s2, -p);
            neum_add(sum2, c2, p); c2 += e;
        }
        {
            float s3 = s + 3.f;
            float p = v.w * s3;
            float e = fmaf(v.w, s3, -p);
            neum_add(sum3, c3, p); c3 += e;
        }
    }
    float S = sum0, C = c0;
    neum_add(S, C, sum1); C += c1;
    neum_add(S, C, sum2); C += c2;
    neum_add(S, C, sum3); C += c3;

#pragma unroll
    for (int o = 16; o; o >>= 1) {
        float oh = __shfl_xor_sync(0xffffffffu, S, o);
        float ol = __shfl_xor_sync(0xffffffffu, C, o);
        float tt = S + oh;
        float corr = (fabsf(S) >= fabsf(oh)) ? ((S - tt) + oh) : ((oh - tt) + S);
        S = tt;
        C = C + ol + corr;
    }
    float prop = S + C;

    float am = (float)mmask[warp];
    float act;
    if (t == 0) {
        act = am;
    } else {
        const float4* m1 = (const float4*)(mels + (size_t)warp * F);
        const float4* m0 = (const float4*)(mels + (size_t)(warp - 1) * F);
        float4 x = m1[lane], y = m0[lane];
        float dot = x.x * y.x + x.y * y.y + x.z * y.z + x.w * y.w;
        float n1  = x.x * x.x + x.y * x.y + x.z * x.z + x.w * x.w;
        float n0  = y.x * y.x + y.y * y.y + y.z * y.z + y.w * y.w;
        dot = wred(dot); n1 = wred(n1); n0 = wred(n0);
        float c = dot / (fmaxf(sqrtf(n0), 1e-12f) * fmaxf(sqrtf(n1), 1e-12f));
        float z = 10.f * (0.9f - c);
        act = am / (1.f + __expf(-z));
    }
    if (lane == 0) { g_prop[warp] = prop; g_act[warp] = act; }
}

// ---------------------------------------------------------------------------
// Kernel 2: per-batch scan + rescale (unchanged — validated)
// ---------------------------------------------------------------------------
__global__ void k_scan(const int* __restrict__ mmask,
                       const int* __restrict__ tmask,
                       float* __restrict__ imv_out) {
    int b    = blockIdx.x;
    int tid  = threadIdx.x;       // 256
    int lane = tid & 31, wid = tid >> 5;
    const float* prop = g_prop + b * T2;
    const float* act  = g_act  + b * T2;
    const int*   mm   = mmask  + b * T2;

    __shared__ float  s_imv[T2];
    __shared__ double wsum[8];
    __shared__ int    s_msum, s_tsum;
    __shared__ float  s_scale;
    if (tid == 0) { s_msum = 0; s_tsum = 0; }
    __syncthreads();

    double vals[8];
    double run = 0.0;
    int    msum = 0;
#pragma unroll
    for (int j = 0; j < 8; j++) {
        int t = tid * 8 + j;
        float e = 0.f;
        if (t > 0) {
            e = (prop[t] - prop[t - 1]) * act[t];   // f32, as in reference
            e = fminf(fmaxf(e, 0.f), 1.f);
        }
        run += (double)e;
        vals[j] = run;
        msum += mm[t];
    }
    double tot = run;
#pragma unroll
    for (int o = 1; o < 32; o <<= 1) {
        double n = __shfl_up_sync(0xffffffffu, tot, o);
        if (lane >= o) tot += n;
    }
    if (lane == 31) wsum[wid] = tot;

    msum = wredi(msum);
    if (lane == 0) atomicAdd(&s_msum, msum);
    int tsum = tmask[b * T1 + tid] + tmask[b * T1 + 256 + tid];
    tsum = wredi(tsum);
    if (lane == 0) atomicAdd(&s_tsum, tsum);
    __syncthreads();

    if (wid == 0 && lane < 8) {
        double w = wsum[lane];
#pragma unroll
        for (int o = 1; o < 8; o <<= 1) {
            double n = __shfl_up_sync(0x000000ffu, w, o);
            if (lane >= o) w += n;
        }
        wsum[lane] = w;
    }
    __syncthreads();

    double base = (wid > 0 ? wsum[wid - 1] : 0.0) + (tot - run);
#pragma unroll
    for (int j = 0; j < 8; j++) s_imv[tid * 8 + j] = (float)(base + vals[j]);
    __syncthreads();

    if (tid == 0) {
        int vlen = s_msum;
        g_vlen[b] = vlen;
        int li = vlen - 1; if (li < 0) li = 0;
        float lastv = fmaxf(s_imv[li] * (float)mm[li], 1e-6f);
        float tl = (float)s_tsum;
        s_scale = fmaxf(tl - 1.f, 0.f) / lastv;   // f32 divide, as in ref
    }
    __syncthreads();

    float sc = s_scale;
#pragma unroll
    for (int j = 0; j < 8; j++) {
        int t = tid * 8 + j;
        float v = s_imv[t] * sc * (float)mm[t];   // f32 mul chain, as in ref
        g_imv[b * T2 + t]   = v;
        imv_out[b * T2 + t] = v;
    }
}

// ---------------------------------------------------------------------------
// Kernel 3: per-frame softmax normalizer. Packs (imv, w) where
// w = am * exp(-m) / Z  so gamma = exp(-10 d^2) * w with no guards needed
// (m in [-2.5, 0] for any nonempty window).
// ---------------------------------------------------------------------------
__global__ void k_z(const int* __restrict__ mmask,
                    const int* __restrict__ tmask) {
    int r = blockIdx.x * blockDim.x + threadIdx.x;
    if (r >= NROWS) return;
    int b = r / T2;
    float x  = g_imv[r];
    float am = (float)mmask[r];
    const int* tm = tmask + b * T1;
    int ci = (int)floorf(x + 0.5f);
    float l[9];
    float m = -1e30f;
#pragma unroll
    for (int k = 0; k < 9; k++) {
        int s = ci + k - 4;
        float lv = -1e30f;
        if (s >= 0 && s < T1 && tm[s]) {
            float d = x - (float)s;
            lv = -10.f * d * d;
        }
        l[k] = lv;
        m = fmaxf(m, lv);
    }
    float Z = 0.f;
#pragma unroll
    for (int k = 0; k < 9; k++)
        if (l[k] > -1e29f) Z += __expf(l[k] - m);
    float w = (Z > 0.f) ? am * __expf(-m) / Z : 0.f;
    g_iw[r] = make_float2(x, w);
}

// ---------------------------------------------------------------------------
// Kernel 4: gather. Block = (8 phonemes, 1 batch), 128 threads = F lanes.
// Warp-parallel 32-ary bound search (3 probe rounds), then single-pass:
// gammas computed once into registers -> durations reduced from registers ->
// normalize into shared (tf32) -> mel FMA loop. Fallback chunked path for
// nt > 128 (not taken on this data).
// ---------------------------------------------------------------------------
__global__ void __launch_bounds__(128) k_gather(
        const float* __restrict__ mels,
        const int*   __restrict__ tmask,
        float* __restrict__ aligned,
        float* __restrict__ durs) {
    int b   = blockIdx.y;
    int s0  = blockIdx.x * SPB;
    int tid = threadIdx.x;
    int lane = tid & 31, wid = tid >> 5;
    const float2* iw = g_iw + b * T2;
    int vlen = g_vlen[b];

    __shared__ int   s_rng[2];
    __shared__ float s_g[SPB][132];
    __shared__ float s_tm[SPB];
    __shared__ float s_w4[4][SPB];
    __shared__ float s_dur[SPB];
    if (tid < SPB) s_tm[tid] = (float)tmask[b * T1 + s0 + tid];

    if (wid == 0) {
        int r = wsearch(iw, vlen, (float)s0 - 4.6f, false, lane);
        if (lane == 0) s_rng[0] = r;
    } else if (wid == 1) {
        int r = wsearch(iw, vlen, (float)(s0 + SPB - 1) + 4.6f, true, lane);
        if (lane == 0) s_rng[1] = r;
    }
    __syncthreads();
    int t_lo = s_rng[0], t_hi = s_rng[1];
    int nt = t_hi - t_lo;

    if (nt <= 128) {
        // ---------------- fast single-pass path ----------------
        float g[SPB];
        int t = t_lo + tid;
        if (t < t_hi) {
            float2 v = iw[t];
#pragma unroll
            for (int k = 0; k < SPB; k++) {
                float d = v.x - (float)(s0 + k);
                g[k] = __expf(-10.f * d * d) * v.y * s_tm[k];
            }
        } else {
#pragma unroll
            for (int k = 0; k < SPB; k++) g[k] = 0.f;
        }
        // durations straight from registers
        float durp[SPB];
#pragma unroll
        for (int k = 0; k < SPB; k++) durp[k] = wred(g[k]);
        if (lane == 0) {
#pragma unroll
            for (int k = 0; k < SPB; k++) s_w4[wid][k] = durp[k];
        }
        __syncthreads();
        if (tid < SPB) {
            float d = s_w4[0][tid] + s_w4[1][tid] + s_w4[2][tid] + s_w4[3][tid];
            s_dur[tid] = d;
            durs[b * T1 + s0 + tid] = d * s_tm[tid];
        }
        __syncthreads();
        // normalize into shared (tf32 weights)
#pragma unroll
        for (int k = 0; k < SPB; k++)
            s_g[k][tid] = (t < t_hi) ? tf32r(g[k] / (s_dur[k] + 1e-8f)) : 0.f;
        __syncthreads();

        float acc[SPB];
#pragma unroll
        for (int k = 0; k < SPB; k++) acc[k] = 0.f;
        const float* mp = mels + ((size_t)(b * T2 + t_lo)) * F + tid;
#pragma unroll 8
        for (int tt = 0; tt < nt; tt++) {
            float mv = tf32r(mp[(size_t)tt * F]);
#pragma unroll
            for (int k = 0; k < SPB; k++) acc[k] = fmaf(s_g[k][tt], mv, acc[k]);
        }
#pragma unroll
        for (int k = 0; k < SPB; k++)
            aligned[((size_t)(b * T1 + s0 + k)) * F + tid] = acc[k] * s_tm[k];
    } else {
        // ---------------- fallback chunked two-pass path ----------------
        float durp[SPB];
#pragma unroll
        for (int k = 0; k < SPB; k++) durp[k] = 0.f;
        for (int t = t_lo + tid; t < t_hi; t += 128) {
            float2 v = iw[t];
#pragma unroll
            for (int k = 0; k < SPB; k++) {
                float d = v.x - (float)(s0 + k);
                durp[k] += __expf(-10.f * d * d) * v.y * s_tm[k];
            }
        }
#pragma unroll
        for (int k = 0; k < SPB; k++) durp[k] = wred(durp[k]);
        if (lane == 0) {
#pragma unroll
            for (int k = 0; k < SPB; k++) s_w4[wid][k] = durp[k];
        }
        __syncthreads();
        if (tid < SPB) {
            float d = s_w4[0][tid] + s_w4[1][tid] + s_w4[2][tid] + s_w4[3][tid];
            s_dur[tid] = d;
            durs[b * T1 + s0 + tid] = d * s_tm[tid];
        }
        __syncthreads();
        float invd[SPB];
#pragma unroll
        for (int k = 0; k < SPB; k++) invd[k] = s_dur[k] + 1e-8f;

        float acc[SPB];
#pragma unroll
        for (int k = 0; k < SPB; k++) acc[k] = 0.f;
        for (int t0 = t_lo; t0 < t_hi; t0 += 128) {
            int t = t0 + tid;
            if (t < t_hi) {
                float2 v = iw[t];
#pragma unroll
                for (int k = 0; k < SPB; k++) {
                    float d = v.x - (float)(s0 + k);
                    float g = __expf(-10.f * d * d) * v.y * s_tm[k];
                    s_g[k][tid] = tf32r(g / invd[k]);
                }
            } else {
#pragma unroll
                for (int k = 0; k < SPB; k++) s_g[k][tid] = 0.f;
            }
            __syncthreads();
            int ntc = t_hi - t0; if (ntc > 128) ntc = 128;
            const float* mp = mels + ((size_t)(b * T2 + t0)) * F + tid;
#pragma unroll 8
            for (int tt = 0; tt < ntc; tt++) {
                float mv = tf32r(mp[(size_t)tt * F]);
#pragma unroll
                for (int k = 0; k < SPB; k++) acc[k] = fmaf(s_g[k][tt], mv, acc[k]);
            }
            __syncthreads();
        }
#pragma unroll
        for (int k = 0; k < SPB; k++)
            aligned[((size_t)(b * T1 + s0 + k)) * F + tid] = acc[k] * s_tm[k];
    }
}

// ---------------------------------------------------------------------------
extern "C" void kernel_launch(void* const* d_in, const int* in_sizes, int n_in,
                              void* d_out, int out_size) {
    const float* mels  = (const float*)d_in[0];
    const float* alpha = (const float*)d_in[1];
    const int*   mmask = (const int*)d_in[2];
    const int*   tmask = (const int*)d_in[3];

    float* out_al  = (float*)d_out;                       // [B,T1,F]
    float* out_dur = out_al + (size_t)B * T1 * F;         // [B,T1]
    float* out_imv = out_dur + (size_t)B * T1;            // [B,T2]

    (void)in_sizes; (void)n_in; (void)out_size;

    // 1) proposal + activity : 1 warp per (b,t)
    {
        int warps = NROWS;
        int threads = 256;
        int blocks = (warps * 32 + threads - 1) / threads;
        k_prop_act<<<blocks, threads>>>(mels, alpha, mmask);
    }
    // 2) scan + rescale : 1 block per batch
    k_scan<<<B, 256>>>(mmask, tmask, out_imv);
    // 3) softmax normalizers : full-chip
    k_z<<<NROWS / 256, 256>>>(mmask, tmask);
    // 4) gather: aligned_mels + durations (8 phonemes/block, 1024 blocks)
    {
        dim3 grid(T1 / SPB, B);
        k_gather<<<grid, 128>>>(mels, tmask, out_al, out_dur);
    }
}